// round 16
// baseline (speedup 1.0000x reference)
#include <cuda_runtime.h>
#include <cuda_fp16.h>
#include <math.h>
#include <cstdint>

#define BB 256
#define TT 512
#define II 128
#define HH 256
#define CC 1000

#define NCTA 128     // 64 per layer; groups of 16+16 by batch tile
#define NTH  256

#define APITCH 272                    // bytes per x row (128 halves + 8 pad)
#define WSLICE (16 * APITCH)          // per-warp private 16-row slice
#define XBUF   (8 * WSLICE)           // 34816 B, single x buffer
#define BPK_OFF XBUF
#define SMEM_BYTES (BPK_OFF + 65536)  // + Bpk (layer1: 32 ks * 2KB)

__device__ __half g_xh[BB * TT * II];
__device__ __half g_h0[4][BB][HH];   // 4-deep ring
__device__ __half g_h1[2][BB][HH];
__device__ unsigned int g_c0a[128];  // counters padded 128B apart (CTA arrivals)
__device__ unsigned int g_c1a[128];

__device__ __forceinline__ float th_(float x) {
    float r;
    asm("tanh.approx.f32 %0, %1;" : "=f"(r) : "f"(x));
    return r;
}
__device__ __forceinline__ float sigm_(float x) { return fmaf(th_(0.5f * x), 0.5f, 0.5f); }

__device__ __forceinline__ uint32_t smem_u32(const void* p) {
    uint32_t a;
    asm("{ .reg .u64 t; cvta.to.shared.u64 t, %1; cvt.u32.u64 %0, t; }" : "=r"(a) : "l"(p));
    return a;
}

// per-WARP wait until *p >= v (lane 0 polls, syncwarp broadcasts)
__device__ __forceinline__ void wait_ge_w(unsigned int* p, int v) {
    if (v > 0) {
        if ((threadIdx.x & 31) == 0) {
            unsigned int cur;
            int n = 0;
            for (;;) {
                asm volatile("ld.global.acquire.gpu.u32 %0, [%1];" : "=r"(cur) : "l"(p) : "memory");
                if ((int)cur >= v) break;
                if (++n > 4) __nanosleep(40);
            }
        }
        __syncwarp();
    }
}

// CTA-level arrival (round-13 proven): fence + bar + single release-RED
__device__ __forceinline__ void arrive(unsigned int* p) {
    __threadfence();
    __syncthreads();
    if (threadIdx.x == 0)
        asm volatile("red.release.gpu.global.add.u32 [%0], %1;" :: "l"(p), "r"(1u) : "memory");
}

#define CP_COMMIT() asm volatile("cp.async.commit_group;" ::: "memory")
#define CP_WAIT0()  asm volatile("cp.async.wait_group 0;" ::: "memory")

// per-WARP x staging into the warp's PRIVATE slice (single buffer)
__device__ __forceinline__ void issue_x(
    uint32_t abase, const __half* __restrict__ xbase,
    int mt, int ms, int w, int lane)
{
    uint32_t dst = abase + (uint32_t)w * WSLICE;
#pragma unroll
    for (int j = 0; j < 8; j++) {
        int seg = lane + j * 32;          // 16 rows x 16 segments
        int r   = seg >> 4;
        int sgc = seg & 15;
        const __half* g = xbase + (long)(mt * 64 + ms * 16 + r) * ((long)TT * II) + sgc * 8;
        uint32_t sa = dst + (uint32_t)(r * APITCH + sgc * 16);
        asm volatile("cp.async.cg.shared.global [%0], [%1], 16;" :: "r"(sa), "l"(g) : "memory");
    }
    CP_COMMIT();
}

#define MMA16816(acc, a0, a1, a2, a3, b0, b1) \
    asm volatile( \
        "mma.sync.aligned.m16n8k16.row.col.f32.f16.f16.f32 " \
        "{%0,%1,%2,%3}, {%4,%5,%6,%7}, {%8,%9}, {%0,%1,%2,%3};" \
        : "+f"((acc)[0]), "+f"((acc)[1]), "+f"((acc)[2]), "+f"((acc)[3]) \
        : "r"(a0), "r"(a1), "r"(a2), "r"(a3), "r"(b0), "r"(b1))

// h chunk (128 cols) computed with A loaded DIRECTLY from global (L2, .cg)
// into m16n8k16 fragments: a0=(r0,c), a1=(r0+8,c), a2=(r0,c+8), a3=(r0+8,c+8)
__device__ __forceinline__ void compute_ldg(
    float acc[4][4], const __half* __restrict__ hsrc, int r0,
    int kbase, const uint32_t* __restrict__ Bpk, int nh, int lane, int ksg0)
{
    const uint32_t* p0 = (const uint32_t*)(hsrc + (size_t)r0 * HH + kbase + (lane & 3) * 2);
    const uint32_t* p1 = (const uint32_t*)((const char*)p0 + 8 * HH * 2);
#pragma unroll
    for (int ks = 0; ks < 8; ks++) {
        uint32_t a0 = __ldcg(p0 + ks * 8);
        uint32_t a1 = __ldcg(p1 + ks * 8);
        uint32_t a2 = __ldcg(p0 + ks * 8 + 4);
        uint32_t a3 = __ldcg(p1 + ks * 8 + 4);
        const int ksg = ksg0 + ks;
#pragma unroll
        for (int ntl = 0; ntl < 4; ntl++) {
            uint2 bv = *(const uint2*)(Bpk + ((ksg * 8 + nh * 4 + ntl) * 32 + lane) * 2);
            MMA16816(acc[ntl], a0, a1, a2, a3, bv.x, bv.y);
        }
    }
}

// h chunk with B from registers (layer1 chunk 0)
__device__ __forceinline__ void compute_ldg_breg(
    float acc[4][4], const __half* __restrict__ hsrc, int r0,
    int kbase, const uint32_t* __restrict__ breg, int lane)
{
    const uint32_t* p0 = (const uint32_t*)(hsrc + (size_t)r0 * HH + kbase + (lane & 3) * 2);
    const uint32_t* p1 = (const uint32_t*)((const char*)p0 + 8 * HH * 2);
#pragma unroll
    for (int ks = 0; ks < 8; ks++) {
        uint32_t a0 = __ldcg(p0 + ks * 8);
        uint32_t a1 = __ldcg(p1 + ks * 8);
        uint32_t a2 = __ldcg(p0 + ks * 8 + 4);
        uint32_t a3 = __ldcg(p1 + ks * 8 + 4);
#pragma unroll
        for (int ntl = 0; ntl < 4; ntl++) {
            MMA16816(acc[ntl], a0, a1, a2, a3,
                     breg[(ks * 4 + ntl) * 2], breg[(ks * 4 + ntl) * 2 + 1]);
        }
    }
}

// x chunk (chunk 0, layer0): A via ldmatrix from smem, B from registers
__device__ __forceinline__ void compute_x_reg(
    float acc[4][4], uint32_t smb, const uint32_t* __restrict__ breg,
    uint32_t rowoff)
{
    CP_WAIT0();
    const uint32_t ab = smb + rowoff;
#pragma unroll
    for (int ks = 0; ks < 8; ks++) {
        uint32_t a0, a1, a2, a3;
        asm volatile(
            "ldmatrix.sync.aligned.m8n8.x4.shared.b16 {%0,%1,%2,%3}, [%4];"
            : "=r"(a0), "=r"(a1), "=r"(a2), "=r"(a3)
            : "r"(ab + (uint32_t)(ks * 32)));
#pragma unroll
        for (int ntl = 0; ntl < 4; ntl++) {
            MMA16816(acc[ntl], a0, a1, a2, a3,
                     breg[(ks * 4 + ntl) * 2], breg[(ks * 4 + ntl) * 2 + 1]);
        }
    }
}

__global__ __launch_bounds__(NTH, 1) void lstm_mma(
    const float* __restrict__ Wih0, const float* __restrict__ Whh0,
    const float* __restrict__ bih0, const float* __restrict__ bhh0,
    const float* __restrict__ Wih1, const float* __restrict__ Whh1,
    const float* __restrict__ bih1, const float* __restrict__ bhh1)
{
    extern __shared__ char smem[];
    const uint32_t smb = smem_u32(smem);
    const int tid = threadIdx.x;
    const int cid = blockIdx.x;
    const int layer = cid >> 6;
    const int lb = cid & 63;
    const int mt = lb >> 4;       // batch tile (64 rows) == group
    const int nt = lb & 15;       // unit tile (16 units)

    const int K0  = layer ? HH : II;
    const int nks = layer ? 32 : 24;

    const float* WA = layer ? Wih1 : Wih0;
    const float* WB = layer ? Whh1 : Whh0;
    const float* bA = layer ? bih1 : bih0;
    const float* bB = layer ? bhh1 : bhh0;

    const int w    = tid >> 5;
    const int lane = tid & 31;
    const int ms   = w & 3;
    const int nh   = w >> 2;
    const int g    = lane >> 2;
    const int tg   = lane & 3;

    // ---- pack fp16 weights into Bpk[ks][nti][lane][2] ----
    uint32_t* Bpk = (uint32_t*)(smem + BPK_OFF);
    for (int idx = tid; idx < nks * 512; idx += NTH) {
        int j   = idx & 1;
        int ln  = (idx >> 1) & 31;
        int nti = (idx >> 6) & 7;
        int ks  = idx >> 9;
        int lg  = ln >> 2, ltg = ln & 3;
        int k   = ks * 16 + j * 8 + ltg * 2;
        int s   = 8 * nti + lg;
        int row = (s & 3) * HH + nt * 16 + (s >> 2);
        float w0, w1;
        if (k < K0) { w0 = WA[(size_t)row * K0 + k];        w1 = WA[(size_t)row * K0 + k + 1]; }
        else        { w0 = WB[(size_t)row * HH + (k - K0)]; w1 = WB[(size_t)row * HH + (k - K0) + 1]; }
        __half2 hw = __floats2half2_rn(w0, w1);
        Bpk[idx] = *(uint32_t*)&hw;
    }

    // ---- biases: 4 ntiles x 4 gates ----
    float biasr[4][4];
#pragma unroll
    for (int ntl = 0; ntl < 4; ntl++) {
        int ugl = nt * 16 + 8 * nh + 2 * ntl + (tg >> 1);
#pragma unroll
        for (int gt = 0; gt < 4; gt++)
            biasr[ntl][gt] = bA[gt * HH + ugl] + bB[gt * HH + ugl];
    }
    __syncthreads();   // Bpk ready

    // ---- chunk-0 B weights -> registers (constant across all 512 steps) ----
    uint32_t breg[64];
#pragma unroll
    for (int ks = 0; ks < 8; ks++)
#pragma unroll
        for (int ntl = 0; ntl < 4; ntl++) {
            uint2 bv = *(const uint2*)(Bpk + ((ks * 8 + nh * 4 + ntl) * 32 + lane) * 2);
            breg[(ks * 4 + ntl) * 2]     = bv.x;
            breg[(ks * 4 + ntl) * 2 + 1] = bv.y;
        }

    // x-fragment rowoff inside the warp's private slice
    const int lrowl = (lane & 7) + ((lane >> 3) & 1) * 8;
    const uint32_t rowoff = (uint32_t)(w * WSLICE + lrowl * APITCH + ((lane >> 4) & 1) * 16);

    // LDG fragment base row (global batch)
    const int r0 = mt * 64 + ms * 16 + (lane >> 2);

    const bool even = !(tg & 1);
    const int rl = ms * 16 + g + (even ? 0 : 8);
    const int rowg = mt * 64 + rl;

    float cst[4];
#pragma unroll
    for (int q = 0; q < 4; q++) cst[q] = 0.f;

    unsigned int* c0p = &g_c0a[mt * 32];
    unsigned int* c1p = &g_c1a[mt * 32];

    if (layer == 0)
        issue_x(smb, g_xh, mt, ms, w, lane);   // prologue: stage x step 0

    for (int step = 0; step < TT; step++) {
        float acc[4][4];
#pragma unroll
        for (int q = 0; q < 4; q++)
#pragma unroll
            for (int i = 0; i < 4; i++) acc[q][i] = 0.f;

        __half* hout;
        if (layer == 0) {
            const __half* h0prev = &g_h0[step & 3][0][0];
            hout = &g_h0[(step + 1) & 3][0][0];
            // x chunk: counter-independent -> compute BEFORE any wait
            compute_x_reg(acc, smb, breg, rowoff);
            if (step + 1 < TT)
                issue_x(smb, g_xh + (size_t)(step + 1) * II, mt, ms, w, lane);
            wait_ge_w(c0p, 16 * step);               // own-group prev h0
            compute_ldg(acc, h0prev, r0, 0,   Bpk, nh, lane, 8);
            compute_ldg(acc, h0prev, r0, 128, Bpk, nh, lane, 16);
            wait_ge_w(c1p, 16 * (step - 3));         // anti-overwrite of h0 ring
        } else {
            const __half* h0cur  = &g_h0[(step + 1) & 3][0][0];
            const __half* h1prev = &g_h1[step & 1][0][0];
            hout = &g_h1[(step + 1) & 1][0][0];
            wait_ge_w(c0p, 16 * (step + 1));         // layer0 runs ahead -> usually instant
            compute_ldg_breg(acc, h0cur, r0, 0, breg, lane);
            compute_ldg(acc, h0cur, r0, 128, Bpk, nh, lane, 8);
            wait_ge_w(c1p, 16 * step);               // own-group prev h1
            compute_ldg(acc, h1prev, r0, 0,   Bpk, nh, lane, 16);
            compute_ldg(acc, h1prev, r0, 128, Bpk, nh, lane, 24);
        }

        // epilogue: quad-exchange gates, activations, state update
#pragma unroll
        for (int ntl = 0; ntl < 4; ntl++) {
            float e0 = __shfl_xor_sync(0xffffffffu, acc[ntl][0], 1);
            float e1 = __shfl_xor_sync(0xffffffffu, acc[ntl][1], 1);
            float e2 = __shfl_xor_sync(0xffffffffu, acc[ntl][2], 1);
            float e3 = __shfl_xor_sync(0xffffffffu, acc[ntl][3], 1);
            float pi = (even ? acc[ntl][0] : e2) + biasr[ntl][0];
            float pf = (even ? acc[ntl][1] : e3) + biasr[ntl][1];
            float pg = (even ? e0 : acc[ntl][2]) + biasr[ntl][2];
            float po = (even ? e1 : acc[ntl][3]) + biasr[ntl][3];
            float cn = sigm_(pf) * cst[ntl] + sigm_(pi) * th_(pg);
            cst[ntl] = cn;
            float hv = sigm_(po) * th_(cn);
            int ug = nt * 16 + 8 * nh + 2 * ntl + (tg >> 1);
            hout[(size_t)rowg * HH + ug] = __float2half_rn(hv);
        }
        arrive(layer ? c1p : c0p);
    }
}

__global__ void convert_x(const float* __restrict__ x) {
    int idx = blockIdx.x * blockDim.x + threadIdx.x;
    int stride = gridDim.x * blockDim.x;
    if (idx < 128) { g_c0a[idx] = 0u; g_c1a[idx] = 0u; }
    __half2* dst = (__half2*)g_xh;
    const float2* src = (const float2*)x;
    for (int i = idx; i < BB * TT * II / 2; i += stride) {
        float2 v = src[i];
        dst[i] = __floats2half2_rn(v.x, v.y);
    }
    uint32_t* z0 = (uint32_t*)&g_h0[0][0][0];
    uint32_t* z1 = (uint32_t*)&g_h1[0][0][0];
    for (int i = idx; i < BB * HH / 2; i += stride) { z0[i] = 0u; z1[i] = 0u; }
}

// tiled classifier: out[256,1000] = h1 @ fcW^T + fcb
__global__ __launch_bounds__(256) void classifier2(
    const float* __restrict__ fcW, const float* __restrict__ fcb,
    float* __restrict__ out)
{
    __shared__ float hs[32][68];
    __shared__ float ws[32][68];
    const int bt = blockIdx.x;
    const int ct = blockIdx.y;
    const int tid = threadIdx.x;
    const int bq = tid >> 4, cq = tid & 15;
    float acc[4][4];
#pragma unroll
    for (int i = 0; i < 4; i++)
#pragma unroll
        for (int j = 0; j < 4; j++) acc[i][j] = 0.f;

    for (int k0 = 0; k0 < HH; k0 += 32) {
        __syncthreads();
        for (int i = tid; i < 64 * 32; i += 256) {
            int b = i >> 5, k = i & 31;
            hs[k][b] = __half2float(g_h1[0][bt * 64 + b][k0 + k]);
        }
        for (int i = tid; i < 64 * 32; i += 256) {
            int c = i >> 5, k = i & 31;
            int gc = ct * 64 + c;
            ws[k][c] = (gc < CC) ? fcW[(size_t)gc * HH + k0 + k] : 0.f;
        }
        __syncthreads();
#pragma unroll
        for (int k = 0; k < 32; k++) {
            float a[4], wv[4];
#pragma unroll
            for (int i = 0; i < 4; i++) a[i] = hs[k][bq * 4 + i];
#pragma unroll
            for (int j = 0; j < 4; j++) wv[j] = ws[k][cq * 4 + j];
#pragma unroll
            for (int i = 0; i < 4; i++)
#pragma unroll
                for (int j = 0; j < 4; j++)
                    acc[i][j] = fmaf(a[i], wv[j], acc[i][j]);
        }
    }
#pragma unroll
    for (int i = 0; i < 4; i++) {
        int b = bt * 64 + bq * 4 + i;
#pragma unroll
        for (int j = 0; j < 4; j++) {
            int c = ct * 64 + cq * 4 + j;
            if (c < CC) out[(size_t)b * CC + c] = acc[i][j] + fcb[c];
        }
    }
}

extern "C" void kernel_launch(void* const* d_in, const int* in_sizes, int n_in,
                              void* d_out, int out_size)
{
    const float* x    = (const float*)d_in[0];
    const float* Wih0 = (const float*)d_in[1];
    const float* Whh0 = (const float*)d_in[2];
    const float* bih0 = (const float*)d_in[3];
    const float* bhh0 = (const float*)d_in[4];
    const float* Wih1 = (const float*)d_in[5];
    const float* Whh1 = (const float*)d_in[6];
    const float* bih1 = (const float*)d_in[7];
    const float* bhh1 = (const float*)d_in[8];
    const float* fcW  = (const float*)d_in[9];
    const float* fcb  = (const float*)d_in[10];
    float* out = (float*)d_out;

    convert_x<<<4096, 256>>>(x);
    cudaFuncSetAttribute(lstm_mma, cudaFuncAttributeMaxDynamicSharedMemorySize, SMEM_BYTES);
    lstm_mma<<<NCTA, NTH, SMEM_BYTES>>>(Wih0, Whh0, bih0, bhh0,
                                        Wih1, Whh1, bih1, bhh1);
    classifier2<<<dim3(4, 16), 256>>>(fcW, fcb, out);
}

// round 17
// speedup vs baseline: 2.5866x; 2.5866x over previous
#include <cuda_runtime.h>
#include <cuda_fp16.h>
#include <math.h>
#include <cstdint>

#define BB 256
#define TT 512
#define II 128
#define HH 256
#define CC 1000

#define NCTA 128     // 64 per layer; groups of 16+16 by batch tile
#define NTH  256
#define KCH  128     // K halves per chunk (8 k16 steps)
#define NBUF 4

#define APITCH 272                   // bytes per A row (128 halves + 8 pad)
#define ABUF  (64 * APITCH)          // 17408 B per A buffer
#define BPK_OFF (NBUF * ABUF)        // 69632
#define SMEM_BYTES (BPK_OFF + 65536) // + max Bpk (layer1: 32 ks * 2KB)

__device__ __half g_xh[BB * TT * II];
__device__ __half g_h0[4][BB][HH];   // 4-deep ring
__device__ __half g_h1[2][BB][HH];
__device__ unsigned int g_c0a[128];  // counters padded 128B apart
__device__ unsigned int g_c1a[128];

__device__ __forceinline__ float th_(float x) {
    float r;
    asm("tanh.approx.f32 %0, %1;" : "=f"(r) : "f"(x));
    return r;
}
__device__ __forceinline__ float sigm_(float x) { return fmaf(th_(0.5f * x), 0.5f, 0.5f); }

__device__ __forceinline__ uint32_t smem_u32(const void* p) {
    uint32_t a;
    asm("{ .reg .u64 t; cvta.to.shared.u64 t, %1; cvt.u32.u64 %0, t; }" : "=r"(a) : "l"(p));
    return a;
}

// per-WARP wait until *p >= v (lane 0 polls, syncwarp broadcasts)
__device__ __forceinline__ void wait_ge_w(unsigned int* p, int v) {
    if (v > 0) {
        if ((threadIdx.x & 31) == 0) {
            unsigned int cur;
            int n = 0;
            for (;;) {
                asm volatile("ld.global.acquire.gpu.u32 %0, [%1];" : "=r"(cur) : "l"(p) : "memory");
                if ((int)cur >= v) break;
                if (++n > 4) __nanosleep(40);
            }
        }
        __syncwarp();
    }
}

// CTA-level arrival (proven): fence + bar + single release-RED
__device__ __forceinline__ void arrive(unsigned int* p) {
    __threadfence();
    __syncthreads();
    if (threadIdx.x == 0)
        asm volatile("red.release.gpu.global.add.u32 [%0], %1;" :: "l"(p), "r"(1u) : "memory");
}

#define CP_COMMIT() asm volatile("cp.async.commit_group;" ::: "memory")
__device__ __forceinline__ void cp_wait_n(int n) {
    switch (n) {
    case 0: asm volatile("cp.async.wait_group 0;" ::: "memory"); break;
    case 1: asm volatile("cp.async.wait_group 1;" ::: "memory"); break;
    case 2: asm volatile("cp.async.wait_group 2;" ::: "memory"); break;
    default: asm volatile("cp.async.wait_group 3;" ::: "memory"); break;
    }
}

// per-WARP staging: warp stages ONLY its own 16 A rows (ms slice) of chunk c.
// The two warps sharing an M-slice write identical duplicate bytes (benign).
__device__ __forceinline__ void issue_chunk_w(
    uint32_t abase, int c, int K0,
    const __half* __restrict__ seg0, long rs0,
    const __half* __restrict__ seg1,
    int mt, int ms, int lane)
{
    const __half* base; long rs; int koff;
    if (c * KCH < K0) { base = seg0; rs = rs0; koff = c * KCH; }
    else              { base = seg1; rs = HH;  koff = c * KCH - K0; }
    uint32_t dst = abase + (uint32_t)(c & (NBUF - 1)) * ABUF;
#pragma unroll
    for (int j = 0; j < 8; j++) {
        int seg = lane + j * 32;          // 0..255 : 16 rows x 16 segments
        int r   = seg >> 4;
        int sgc = seg & 15;
        const __half* g = base + (long)(mt * 64 + ms * 16 + r) * rs + koff + sgc * 8;
        uint32_t sa = dst + (uint32_t)((ms * 16 + r) * APITCH + sgc * 16);
        asm volatile("cp.async.cg.shared.global [%0], [%1], 16;" :: "r"(sa), "l"(g) : "memory");
    }
    CP_COMMIT();
}

#define MMA16816(acc, a0, a1, a2, a3, b0, b1) \
    asm volatile( \
        "mma.sync.aligned.m16n8k16.row.col.f32.f16.f16.f32 " \
        "{%0,%1,%2,%3}, {%4,%5,%6,%7}, {%8,%9}, {%0,%1,%2,%3};" \
        : "+f"((acc)[0]), "+f"((acc)[1]), "+f"((acc)[2]), "+f"((acc)[3]) \
        : "r"(a0), "r"(a1), "r"(a2), "r"(a3), "r"(b0), "r"(b1))

// compute chunk c (c>=2), B from smem; no CTA barrier (warp-local staging)
__device__ __forceinline__ void compute_one(
    float acc[4][4], uint32_t smb, const uint32_t* __restrict__ Bpk,
    uint32_t rowoff, int nh, int lane, int c, int wait_n)
{
    cp_wait_n(wait_n);
    const uint32_t ab = smb + (uint32_t)(c & (NBUF - 1)) * ABUF + rowoff;
#pragma unroll
    for (int ks = 0; ks < 8; ks++) {
        uint32_t a0, a1, a2, a3;
        asm volatile(
            "ldmatrix.sync.aligned.m8n8.x4.shared.b16 {%0,%1,%2,%3}, [%4];"
            : "=r"(a0), "=r"(a1), "=r"(a2), "=r"(a3)
            : "r"(ab + (uint32_t)(ks * 32)));
        const int ksg = c * 8 + ks;
#pragma unroll
        for (int ntl = 0; ntl < 4; ntl++) {
            uint2 bv = *(const uint2*)(Bpk + ((ksg * 8 + nh * 4 + ntl) * 32 + lane) * 2);
            MMA16816(acc[ntl], a0, a1, a2, a3, bv.x, bv.y);
        }
    }
}

// compute chunk c (0 or 1) with B fully register-resident
__device__ __forceinline__ void compute_creg(
    float acc[4][4], uint32_t smb, const uint32_t* __restrict__ breg,
    uint32_t rowoff, int c, int wait_n)
{
    cp_wait_n(wait_n);
    const uint32_t ab = smb + (uint32_t)c * ABUF + rowoff;
#pragma unroll
    for (int ks = 0; ks < 8; ks++) {
        uint32_t a0, a1, a2, a3;
        asm volatile(
            "ldmatrix.sync.aligned.m8n8.x4.shared.b16 {%0,%1,%2,%3}, [%4];"
            : "=r"(a0), "=r"(a1), "=r"(a2), "=r"(a3)
            : "r"(ab + (uint32_t)(ks * 32)));
#pragma unroll
        for (int ntl = 0; ntl < 4; ntl++) {
            MMA16816(acc[ntl], a0, a1, a2, a3,
                     breg[(ks * 4 + ntl) * 2], breg[(ks * 4 + ntl) * 2 + 1]);
        }
    }
}

__global__ __launch_bounds__(NTH, 1) void lstm_mma(
    const float* __restrict__ Wih0, const float* __restrict__ Whh0,
    const float* __restrict__ bih0, const float* __restrict__ bhh0,
    const float* __restrict__ Wih1, const float* __restrict__ Whh1,
    const float* __restrict__ bih1, const float* __restrict__ bhh1)
{
    extern __shared__ char smem[];
    const uint32_t smb = smem_u32(smem);
    const int tid = threadIdx.x;
    const int cid = blockIdx.x;
    const int layer = cid >> 6;
    const int lb = cid & 63;
    const int mt = lb >> 4;       // batch tile (64 rows) == group
    const int nt = lb & 15;       // unit tile (16 units)

    const int K0  = layer ? HH : II;
    const int nks = layer ? 32 : 24;

    const float* WA = layer ? Wih1 : Wih0;
    const float* WB = layer ? Whh1 : Whh0;
    const float* bA = layer ? bih1 : bih0;
    const float* bB = layer ? bhh1 : bhh0;

    const int w    = tid >> 5;
    const int lane = tid & 31;
    const int ms   = w & 3;
    const int nh   = w >> 2;
    const int g    = lane >> 2;
    const int tg   = lane & 3;

    // ---- pack fp16 weights into Bpk[ks][nti][lane][2] ----
    uint32_t* Bpk = (uint32_t*)(smem + BPK_OFF);
    for (int idx = tid; idx < nks * 512; idx += NTH) {
        int j   = idx & 1;
        int ln  = (idx >> 1) & 31;
        int nti = (idx >> 6) & 7;
        int ks  = idx >> 9;
        int lg  = ln >> 2, ltg = ln & 3;
        int k   = ks * 16 + j * 8 + ltg * 2;
        int s   = 8 * nti + lg;
        int row = (s & 3) * HH + nt * 16 + (s >> 2);
        float w0, w1;
        if (k < K0) { w0 = WA[(size_t)row * K0 + k];        w1 = WA[(size_t)row * K0 + k + 1]; }
        else        { w0 = WB[(size_t)row * HH + (k - K0)]; w1 = WB[(size_t)row * HH + (k - K0) + 1]; }
        __half2 hw = __floats2half2_rn(w0, w1);
        Bpk[idx] = *(uint32_t*)&hw;
    }

    // ---- biases: 4 ntiles x 4 gates ----
    float biasr[4][4];
#pragma unroll
    for (int ntl = 0; ntl < 4; ntl++) {
        int ugl = nt * 16 + 8 * nh + 2 * ntl + (tg >> 1);
#pragma unroll
        for (int gt = 0; gt < 4; gt++)
            biasr[ntl][gt] = bA[gt * HH + ugl] + bB[gt * HH + ugl];
    }
    __syncthreads();   // Bpk ready

    // ---- chunk-0 AND chunk-1 B weights -> registers (step-invariant) ----
    uint32_t breg[64], breg2[64];
#pragma unroll
    for (int ks = 0; ks < 8; ks++)
#pragma unroll
        for (int ntl = 0; ntl < 4; ntl++) {
            uint2 bv = *(const uint2*)(Bpk + ((ks * 8 + nh * 4 + ntl) * 32 + lane) * 2);
            breg[(ks * 4 + ntl) * 2]     = bv.x;
            breg[(ks * 4 + ntl) * 2 + 1] = bv.y;
            uint2 bv2 = *(const uint2*)(Bpk + (((ks + 8) * 8 + nh * 4 + ntl) * 32 + lane) * 2);
            breg2[(ks * 4 + ntl) * 2]     = bv2.x;
            breg2[(ks * 4 + ntl) * 2 + 1] = bv2.y;
        }

    const int lrow = ms * 16 + (lane & 7) + ((lane >> 3) & 1) * 8;
    const uint32_t rowoff = (uint32_t)(lrow * APITCH + ((lane >> 4) & 1) * 16);

    const bool even = !(tg & 1);
    const int rl = ms * 16 + g + (even ? 0 : 8);
    const int rowg = mt * 64 + rl;

    float cst[4];
#pragma unroll
    for (int q = 0; q < 4; q++) cst[q] = 0.f;

    unsigned int* c0p = &g_c0a[mt * 32];
    unsigned int* c1p = &g_c1a[mt * 32];

    for (int step = 0; step < TT; step++) {
        float acc[4][4];
#pragma unroll
        for (int q = 0; q < 4; q++)
#pragma unroll
            for (int i = 0; i < 4; i++) acc[q][i] = 0.f;

        __half* hout;
        if (layer == 0) {
            const __half* seg0 = g_xh + (size_t)step * II;
            const __half* seg1 = &g_h0[step & 3][0][0];
            hout = &g_h0[(step + 1) & 3][0][0];
            // chunk0 (pure x) issued before the wait -> load overlaps poll
            issue_chunk_w(smb, 0, K0, seg0, (long)TT * II, seg1, mt, ms, lane);
            wait_ge_w(c0p, 16 * step);               // own-group prev h0
            issue_chunk_w(smb, 1, K0, seg0, (long)TT * II, seg1, mt, ms, lane);
            issue_chunk_w(smb, 2, K0, seg0, (long)TT * II, seg1, mt, ms, lane);
            compute_creg(acc, smb, breg, rowoff, 0, 2);
            compute_creg(acc, smb, breg2, rowoff, 1, 1);
            compute_one(acc, smb, Bpk, rowoff, nh, lane, 2, 0);
            wait_ge_w(c1p, 16 * (step - 3));         // anti-overwrite of h0 ring
        } else {
            const __half* seg0 = &g_h0[(step + 1) & 3][0][0];
            const __half* seg1 = &g_h1[step & 1][0][0];
            hout = &g_h1[(step + 1) & 1][0][0];
            wait_ge_w(c0p, 16 * (step + 1));         // layer0 runs ahead -> usually instant
            issue_chunk_w(smb, 0, K0, seg0, HH, seg1, mt, ms, lane);
            issue_chunk_w(smb, 1, K0, seg0, HH, seg1, mt, ms, lane);
            compute_creg(acc, smb, breg, rowoff, 0, 1);  // hides the c1 wait below
            wait_ge_w(c1p, 16 * step);               // own-group prev h1
            issue_chunk_w(smb, 2, K0, seg0, HH, seg1, mt, ms, lane);
            issue_chunk_w(smb, 3, K0, seg0, HH, seg1, mt, ms, lane);
            compute_creg(acc, smb, breg2, rowoff, 1, 2);
            compute_one(acc, smb, Bpk, rowoff, nh, lane, 2, 1);
            compute_one(acc, smb, Bpk, rowoff, nh, lane, 3, 0);
        }

        // epilogue: quad-exchange gates, activations, state update
#pragma unroll
        for (int ntl = 0; ntl < 4; ntl++) {
            float e0 = __shfl_xor_sync(0xffffffffu, acc[ntl][0], 1);
            float e1 = __shfl_xor_sync(0xffffffffu, acc[ntl][1], 1);
            float e2 = __shfl_xor_sync(0xffffffffu, acc[ntl][2], 1);
            float e3 = __shfl_xor_sync(0xffffffffu, acc[ntl][3], 1);
            float pi = (even ? acc[ntl][0] : e2) + biasr[ntl][0];
            float pf = (even ? acc[ntl][1] : e3) + biasr[ntl][1];
            float pg = (even ? e0 : acc[ntl][2]) + biasr[ntl][2];
            float po = (even ? e1 : acc[ntl][3]) + biasr[ntl][3];
            float cn = sigm_(pf) * cst[ntl] + sigm_(pi) * th_(pg);
            cst[ntl] = cn;
            float hv = sigm_(po) * th_(cn);
            int ug = nt * 16 + 8 * nh + 2 * ntl + (tg >> 1);
            hout[(size_t)rowg * HH + ug] = __float2half_rn(hv);
        }
        arrive(layer ? c1p : c0p);   // sole CTA barrier per step
    }
}

__global__ void convert_x(const float* __restrict__ x) {
    int idx = blockIdx.x * blockDim.x + threadIdx.x;
    int stride = gridDim.x * blockDim.x;
    if (idx < 128) { g_c0a[idx] = 0u; g_c1a[idx] = 0u; }
    __half2* dst = (__half2*)g_xh;
    const float2* src = (const float2*)x;
    for (int i = idx; i < BB * TT * II / 2; i += stride) {
        float2 v = src[i];
        dst[i] = __floats2half2_rn(v.x, v.y);
    }
    uint32_t* z0 = (uint32_t*)&g_h0[0][0][0];
    uint32_t* z1 = (uint32_t*)&g_h1[0][0][0];
    for (int i = idx; i < BB * HH / 2; i += stride) { z0[i] = 0u; z1[i] = 0u; }
}

// tiled classifier: out[256,1000] = h1 @ fcW^T + fcb
__global__ __launch_bounds__(256) void classifier2(
    const float* __restrict__ fcW, const float* __restrict__ fcb,
    float* __restrict__ out)
{
    __shared__ float hs[32][68];
    __shared__ float ws[32][68];
    const int bt = blockIdx.x;
    const int ct = blockIdx.y;
    const int tid = threadIdx.x;
    const int bq = tid >> 4, cq = tid & 15;
    float acc[4][4];
#pragma unroll
    for (int i = 0; i < 4; i++)
#pragma unroll
        for (int j = 0; j < 4; j++) acc[i][j] = 0.f;

    for (int k0 = 0; k0 < HH; k0 += 32) {
        __syncthreads();
        for (int i = tid; i < 64 * 32; i += 256) {
            int b = i >> 5, k = i & 31;
            hs[k][b] = __half2float(g_h1[0][bt * 64 + b][k0 + k]);
        }
        for (int i = tid; i < 64 * 32; i += 256) {
            int c = i >> 5, k = i & 31;
            int gc = ct * 64 + c;
            ws[k][c] = (gc < CC) ? fcW[(size_t)gc * HH + k0 + k] : 0.f;
        }
        __syncthreads();
#pragma unroll
        for (int k = 0; k < 32; k++) {
            float a[4], wv[4];
#pragma unroll
            for (int i = 0; i < 4; i++) a[i] = hs[k][bq * 4 + i];
#pragma unroll
            for (int j = 0; j < 4; j++) wv[j] = ws[k][cq * 4 + j];
#pragma unroll
            for (int i = 0; i < 4; i++)
#pragma unroll
                for (int j = 0; j < 4; j++)
                    acc[i][j] = fmaf(a[i], wv[j], acc[i][j]);
        }
    }
#pragma unroll
    for (int i = 0; i < 4; i++) {
        int b = bt * 64 + bq * 4 + i;
#pragma unroll
        for (int j = 0; j < 4; j++) {
            int c = ct * 64 + cq * 4 + j;
            if (c < CC) out[(size_t)b * CC + c] = acc[i][j] + fcb[c];
        }
    }
}

extern "C" void kernel_launch(void* const* d_in, const int* in_sizes, int n_in,
                              void* d_out, int out_size)
{
    const float* x    = (const float*)d_in[0];
    const float* Wih0 = (const float*)d_in[1];
    const float* Whh0 = (const float*)d_in[2];
    const float* bih0 = (const float*)d_in[3];
    const float* bhh0 = (const float*)d_in[4];
    const float* Wih1 = (const float*)d_in[5];
    const float* Whh1 = (const float*)d_in[6];
    const float* bih1 = (const float*)d_in[7];
    const float* bhh1 = (const float*)d_in[8];
    const float* fcW  = (const float*)d_in[9];
    const float* fcb  = (const float*)d_in[10];
    float* out = (float*)d_out;

    convert_x<<<4096, 256>>>(x);
    cudaFuncSetAttribute(lstm_mma, cudaFuncAttributeMaxDynamicSharedMemorySize, SMEM_BYTES);
    lstm_mma<<<NCTA, NTH, SMEM_BYTES>>>(Wih0, Whh0, bih0, bhh0,
                                        Wih1, Whh1, bih1, bhh1);
    classifier2<<<dim3(4, 16), 256>>>(fcW, fcb, out);
}